// round 2
// baseline (speedup 1.0000x reference)
#include <cuda_runtime.h>
#include <cstdint>

#define B_    50
#define T_    2048
#define D_    65
#define G4    260      // 4*UNITS
#define KH    36       // half of padded K (2*KH = 72 >= 65)
#define KP    72
#define NL    3
#define NPAIR 25       // batch pairs
#define NTH   520      // 260 cols x 2 K-halves

// Layer outputs: [NL][B][T][D].  Layer 2 slice feeds the dense kernel.
__device__ float g_h[(size_t)NL * B_ * T_ * D_];
// Per-(layer,batch,timestep) ready flags (cleared at start of every launch).
__device__ int   g_flag[NL * B_ * T_];

static __device__ __forceinline__ size_t hidx(int l, int b) {
    return ((size_t)l * B_ + b) * T_ * D_;
}
static __device__ __forceinline__ size_t fidx(int l, int b) {
    return ((size_t)l * B_ + b) * T_;
}

// ---------------------------------------------------------------------------
// math helpers
// ---------------------------------------------------------------------------
__device__ __forceinline__ float sigmoid_f(float x) {
    return 1.0f / (1.0f + __expf(-x));
}
__device__ __forceinline__ float tanh_f(float x) {
    float e = __expf(2.0f * x);
    return 1.0f - 2.0f / (e + 1.0f);
}
__device__ __forceinline__ void ffma2(uint64_t& acc, uint64_t a, uint64_t b) {
    asm("fma.rn.f32x2 %0, %1, %2, %0;" : "+l"(acc) : "l"(a), "l"(b));
}
__device__ __forceinline__ uint64_t fadd2(uint64_t a, uint64_t b) {
    uint64_t r;
    asm("add.rn.f32x2 %0, %1, %2;" : "=l"(r) : "l"(a), "l"(b));
    return r;
}
__device__ __forceinline__ float hsum2(uint64_t v) {
    float lo, hi;
    asm("mov.b64 {%0, %1}, %2;" : "=f"(lo), "=f"(hi) : "l"(v));
    return lo + hi;
}
__device__ __forceinline__ uint64_t pack2(float lo, float hi) {
    uint64_t r;
    asm("mov.b64 %0, {%1, %2};" : "=l"(r) : "f"(lo), "f"(hi));
    return r;
}

// ---------------------------------------------------------------------------
// Flag clear (flags persist across graph replays; must be zeroed each launch)
// ---------------------------------------------------------------------------
__global__ void clear_kernel() {
    int i = blockIdx.x * blockDim.x + threadIdx.x;
    if (i < NL * B_ * T_) g_flag[i] = 0;
}

// ---------------------------------------------------------------------------
// Layer-pipelined LSTM: CTA = (layer l, batch pair p). 520 threads.
// Thread tid: column = tid>>1, K-half = tid&1. Weight halves in registers.
// Layers communicate h(t) via g_h + release/acquire flags in g_flag.
// ---------------------------------------------------------------------------
__global__ void __launch_bounds__(NTH, 1) lstm_kernel(
    const float* __restrict__ x,   // [B, T, D]
    const float* __restrict__ W,   // [D, 4D]
    const float* __restrict__ U,   // [D, 4D]
    const float* __restrict__ b)   // [4D]
{
    __shared__ __align__(16) float inpA[KP], inpB[KP], hA[KP], hB[KP];
    __shared__ float zA[G4], zB[G4];

    const int tid  = threadIdx.x;
    const int col  = tid >> 1;
    const int half = tid & 1;
    const int l    = blockIdx.x / NPAIR;
    const int p    = blockIdx.x % NPAIR;
    const int bA   = 2 * p, bB = 2 * p + 1;

    // ---- weight half-columns into packed registers (once) ----
    uint64_t Wr[KH / 2], Ur[KH / 2];
    const int kbase = half * KH;
#pragma unroll
    for (int i = 0; i < KH / 2; i++) {
        int k = kbase + 2 * i;
        float w0 = (k     < D_) ? W[(size_t)k       * G4 + col] : 0.0f;
        float w1 = (k + 1 < D_) ? W[(size_t)(k + 1) * G4 + col] : 0.0f;
        Wr[i] = pack2(w0, w1);
        float u0 = (k     < D_) ? U[(size_t)k       * G4 + col] : 0.0f;
        float u1 = (k + 1 < D_) ? U[(size_t)(k + 1) * G4 + col] : 0.0f;
        Ur[i] = pack2(u0, u1);
    }
    const float bj   = b[col];
    const int   gsel = col / D_;               // 0=i 1=f 2=g 3=o
    const unsigned smask = (tid >= 512) ? 0xFFu : 0xFFFFFFFFu;  // warp 16 has 8 lanes

    if (tid < KP) { inpA[tid] = 0.f; inpB[tid] = 0.f; hA[tid] = 0.f; hB[tid] = 0.f; }
    float c_state = 0.f;                        // valid for tid<130 (gate threads)

    // loader threads: tid in [256,321) -> batch A, [321,386) -> batch B
    const bool isLoader = (tid >= 256 && tid < 386);
    const bool loadA    = (tid < 321);
    const int  jj       = isLoader ? (loadA ? tid - 256 : tid - 321) : 0;
    const int  lb       = loadA ? bA : bB;
    const float* xp   = x + (size_t)lb * T_ * D_;
    const float* hin  = (l > 0) ? (g_h + hidx(l - 1, lb)) : (const float*)0;
    const int*   fin  = (l > 0) ? (g_flag + fidx(l - 1, lb)) : (const int*)0;

    float* houtA = g_h + hidx(l, bA);
    float* houtB = g_h + hidx(l, bB);
    int*   foutA = g_flag + fidx(l, bA);
    int*   foutB = g_flag + fidx(l, bB);

    __syncthreads();

    for (int t = 0; t < T_; t++) {
        // (i) fetch incoming activation for this timestep (x for l==0, else
        //     spin-acquire on producer flag then read its h). LDG latency is
        //     hidden behind the U-dot below.
        float v = 0.f;
        if (isLoader) {
            if (l == 0) {
                v = xp[(size_t)t * D_ + jj];
            } else {
                const int* fp = fin + t;
                int f;
                do {
                    asm volatile("ld.acquire.gpu.global.b32 %0, [%1];"
                                 : "=r"(f) : "l"(fp) : "memory");
                } while (f == 0);
                v = hin[(size_t)t * D_ + jj];
            }
        }

        // (ii) recurrent dot: aU = U[:,col]_half . h_prev  (both batches)
        uint64_t aUA = 0, aUB = 0;
        {
            const ulonglong2* a2 = reinterpret_cast<const ulonglong2*>(hA + kbase);
            const ulonglong2* b2 = reinterpret_cast<const ulonglong2*>(hB + kbase);
#pragma unroll
            for (int i = 0; i < KH / 4; i++) {
                ulonglong2 va = a2[i], vb = b2[i];
                ffma2(aUA, va.x, Ur[2 * i]); ffma2(aUA, va.y, Ur[2 * i + 1]);
                ffma2(aUB, vb.x, Ur[2 * i]); ffma2(aUB, vb.y, Ur[2 * i + 1]);
            }
        }
        if (isLoader) (loadA ? inpA : inpB)[jj] = v;
        __syncthreads();   // (iii) inp ready

        // (iv) input dot + combine + activation
        uint64_t aWA = 0, aWB = 0;
        {
            const ulonglong2* a2 = reinterpret_cast<const ulonglong2*>(inpA + kbase);
            const ulonglong2* b2 = reinterpret_cast<const ulonglong2*>(inpB + kbase);
#pragma unroll
            for (int i = 0; i < KH / 4; i++) {
                ulonglong2 va = a2[i], vb = b2[i];
                ffma2(aWA, va.x, Wr[2 * i]); ffma2(aWA, va.y, Wr[2 * i + 1]);
                ffma2(aWB, vb.x, Wr[2 * i]); ffma2(aWB, vb.y, Wr[2 * i + 1]);
            }
        }
        float sA = hsum2(fadd2(aWA, aUA));
        float sB = hsum2(fadd2(aWB, aUB));
        sA += __shfl_xor_sync(smask, sA, 1);   // combine K-halves
        sB += __shfl_xor_sync(smask, sB, 1);
        if (half == 0) {
            float za = sA + bj, zb = sB + bj;
            zA[col] = (gsel == 2) ? tanh_f(za) : sigmoid_f(za);
            zB[col] = (gsel == 2) ? tanh_f(zb) : sigmoid_f(zb);
        }
        __syncthreads();   // (v) gates ready

        // (vi) gate combine: tid<65 batch A, 65..129 batch B
        if (tid < 130) {
            bool  gA = tid < 65;
            int   j  = gA ? tid : tid - 65;
            const float* zs = gA ? zA : zB;
            float ig = zs[j], fg = zs[j + D_], gg = zs[j + 2 * D_], og = zs[j + 3 * D_];
            float cn = fg * c_state + ig * gg;
            c_state  = cn;
            float hn = og * tanh_f(cn);
            (gA ? hA : hB)[j] = hn;
            (gA ? houtA : houtB)[(size_t)t * D_ + j] = hn;
        }
        __syncthreads();   // (vii) h_s + global h stores complete (cta scope)

        // (viii) publish: cumulative gpu fence then relaxed flag store
        if (tid == 0) {
            asm volatile("fence.acq_rel.gpu;" ::: "memory");
            asm volatile("st.relaxed.gpu.global.b32 [%0], %1;"
                         :: "l"(foutA + t), "r"(1) : "memory");
        } else if (tid == 32) {
            asm volatile("fence.acq_rel.gpu;" ::: "memory");
            asm volatile("st.relaxed.gpu.global.b32 [%0], %1;"
                         :: "l"(foutB + t), "r"(1) : "memory");
        }
    }
}

// ---------------------------------------------------------------------------
// Dense(65) epilogue: out[r,:] = g_h[2][r,:] @ Wd + bd
// ---------------------------------------------------------------------------
#define ROWS_PB 32
__global__ void __launch_bounds__(260) dense_kernel(
    const float* __restrict__ Wd,
    const float* __restrict__ bd,
    float* __restrict__ out)
{
    __shared__ float Wds[D_ * D_];
    __shared__ float bds[D_];
    __shared__ float hrow[ROWS_PB][D_];

    const int tx  = threadIdx.x;           // 0..64
    const int ty  = threadIdx.y;           // 0..3
    const int tid = ty * D_ + tx;          // 0..259
    const float* hsrc = g_h + (size_t)2 * B_ * T_ * D_;

    for (int i = tid; i < D_ * D_; i += 260) Wds[i] = Wd[i];
    if (tid < D_) bds[tid] = bd[tid];
    const size_t row0 = (size_t)blockIdx.x * ROWS_PB;
    for (int i = tid; i < ROWS_PB * D_; i += 260)
        hrow[i / D_][i % D_] = hsrc[row0 * D_ + i];
    __syncthreads();

    for (int r = ty; r < ROWS_PB; r += 4) {
        float acc = bds[tx];
#pragma unroll
        for (int k = 0; k < D_; k++)
            acc += hrow[r][k] * Wds[k * D_ + tx];
        out[(row0 + r) * D_ + tx] = acc;
    }
}

// ---------------------------------------------------------------------------
extern "C" void kernel_launch(void* const* d_in, const int* in_sizes, int n_in,
                              void* d_out, int out_size)
{
    const float* x  = (const float*)d_in[0];
    const float* W  = (const float*)d_in[1];
    const float* U  = (const float*)d_in[2];
    const float* b  = (const float*)d_in[3];
    const float* Wd = (const float*)d_in[4];
    const float* bd = (const float*)d_in[5];
    float* out = (float*)d_out;

    clear_kernel<<<(NL * B_ * T_ + 511) / 512, 512>>>();
    lstm_kernel<<<NL * NPAIR, NTH>>>(x, W, U, b);
    dense_kernel<<<(B_ * T_) / ROWS_PB, dim3(D_, 4)>>>(Wd, bd, out);
}